// round 9
// baseline (speedup 1.0000x reference)
#include <cuda_runtime.h>

#define BATCH 8
#define INPUT_SIZE 8192
#define HIDDEN_SIZE 8192
#define OUTPUT_SIZE 2048
#define KDIM 16384

// Scratch (allocation-free)
__device__ float g_p1[2][BATCH][HIDDEN_SIZE];    // i2h partials (x-half, h-half)
__device__ float g_p2[4][BATCH][OUTPUT_SIZE];    // h2o partials (4 K-quarters)

// ---------------------------------------------------------------------------
__device__ __forceinline__ void cp_async16(void* smem_dst, const void* gmem_src) {
    unsigned s = (unsigned)__cvta_generic_to_shared(smem_dst);
    asm volatile("cp.async.cg.shared.global [%0], [%1], 16;\n" :: "r"(s), "l"(gmem_src));
}
__device__ __forceinline__ void cp_commit()  { asm volatile("cp.async.commit_group;\n"); }
__device__ __forceinline__ void cp_wait1()   { asm volatile("cp.async.wait_group 1;\n"); }
__device__ __forceinline__ void cp_wait0()   { asm volatile("cp.async.wait_group 0;\n"); }

#define TK  512
#define TK4 (TK / 4)    // 128 float4 per batch per chunk

// ===========================================================================
// Kernel 1: split-K x/h halves.  p1[half][b,row] = in_half[b,:]·W[row, half,:]
// grid = 256 tiles x 2 halves = 512 blocks; 256 thr; 4 rows/warp;
// cp.async double-buffered; 3 blocks/SM.
// ===========================================================================
#define R1 4
#define ROWS_PER_BLOCK_1 (R1 * 8)   // 32
#define TILES1 (HIDDEN_SIZE / ROWS_PER_BLOCK_1)   // 256

__global__ __launch_bounds__(256, 3)
void rnn_i2h_kernel(const float* __restrict__ x,
                    const float* __restrict__ h0,
                    const float* __restrict__ W)      // [HIDDEN_SIZE, KDIM]
{
    __shared__ float4 s_in[2][BATCH][TK4];   // 2 x 16 KB

    const int tid  = threadIdx.x;
    const int lane = tid & 31;
    const int warp = tid >> 5;
    const int tile = blockIdx.x & (TILES1 - 1);
    const int half = blockIdx.x >> 8;
    const int row0 = tile * ROWS_PER_BLOCK_1 + warp * R1;

    const float* in  = half ? h0 : x;
    const int NCHUNK = INPUT_SIZE / TK;     // 16

    float acc[R1][BATCH];
    #pragma unroll
    for (int r = 0; r < R1; r++)
        #pragma unroll
        for (int b = 0; b < BATCH; b++)
            acc[r][b] = 0.0f;

    auto stage = [&](int c, int buf) {
        const float* src = in + c * TK;
        #pragma unroll
        for (int t = 0; t < 4; ++t) {
            int f  = tid + t * 256;
            int b  = f >> 7;            // / TK4
            int k4 = f & (TK4 - 1);
            cp_async16(&s_in[buf][b][k4],
                       (const float4*)(src + (size_t)b * INPUT_SIZE) + k4);
        }
        cp_commit();
    };

    stage(0, 0);

    const size_t hoff = (size_t)half * INPUT_SIZE;
    const float* Wr0 = W + (size_t)(row0 + 0) * KDIM + hoff;
    const float* Wr1 = W + (size_t)(row0 + 1) * KDIM + hoff;
    const float* Wr2 = W + (size_t)(row0 + 2) * KDIM + hoff;
    const float* Wr3 = W + (size_t)(row0 + 3) * KDIM + hoff;

    for (int c = 0; c < NCHUNK; ++c) {
        const int buf = c & 1;
        __syncthreads();
        if (c + 1 < NCHUNK) { stage(c + 1, buf ^ 1); cp_wait1(); }
        else                { cp_wait0(); }
        __syncthreads();

        const float* Wc0 = Wr0 + (size_t)c * TK;
        const float* Wc1 = Wr1 + (size_t)c * TK;
        const float* Wc2 = Wr2 + (size_t)c * TK;
        const float* Wc3 = Wr3 + (size_t)c * TK;

        #pragma unroll
        for (int i = 0; i < TK4 / 32; ++i) {          // 4 strips
            const int k4 = i * 32 + lane;
            float4 w0 = __ldcs((const float4*)Wc0 + k4);
            float4 w1 = __ldcs((const float4*)Wc1 + k4);
            float4 w2 = __ldcs((const float4*)Wc2 + k4);
            float4 w3 = __ldcs((const float4*)Wc3 + k4);

            #pragma unroll
            for (int b = 0; b < BATCH; b++) {
                float4 v = s_in[buf][b][k4];
                acc[0][b] = fmaf(w0.x, v.x, acc[0][b]);
                acc[0][b] = fmaf(w0.y, v.y, acc[0][b]);
                acc[0][b] = fmaf(w0.z, v.z, acc[0][b]);
                acc[0][b] = fmaf(w0.w, v.w, acc[0][b]);
                acc[1][b] = fmaf(w1.x, v.x, acc[1][b]);
                acc[1][b] = fmaf(w1.y, v.y, acc[1][b]);
                acc[1][b] = fmaf(w1.z, v.z, acc[1][b]);
                acc[1][b] = fmaf(w1.w, v.w, acc[1][b]);
                acc[2][b] = fmaf(w2.x, v.x, acc[2][b]);
                acc[2][b] = fmaf(w2.y, v.y, acc[2][b]);
                acc[2][b] = fmaf(w2.z, v.z, acc[2][b]);
                acc[2][b] = fmaf(w2.w, v.w, acc[2][b]);
                acc[3][b] = fmaf(w3.x, v.x, acc[3][b]);
                acc[3][b] = fmaf(w3.y, v.y, acc[3][b]);
                acc[3][b] = fmaf(w3.z, v.z, acc[3][b]);
                acc[3][b] = fmaf(w3.w, v.w, acc[3][b]);
            }
        }
    }

    #pragma unroll
    for (int r = 0; r < R1; r++)
        #pragma unroll
        for (int b = 0; b < BATCH; b++)
            #pragma unroll
            for (int off = 16; off > 0; off >>= 1)
                acc[r][b] += __shfl_xor_sync(0xffffffffu, acc[r][b], off);

    #pragma unroll
    for (int r = 0; r < R1; r++) {
        const int row = row0 + r;
        #pragma unroll
        for (int b = 0; b < BATCH; b++)
            if (lane == b)
                g_p1[half][b][row] = acc[r][b];
    }
}

// ===========================================================================
// Kernel 2: h2o GEMV, split-K x4; staging FUSES the i2h reduction:
//   v[b,k] = tanh(p1[0][b,k] + p1[1][b,k] + bias1[k])   (all L2-resident)
// grid = 128 tiles x 4 quarters = 512 blocks; 2 rows/warp; 4 blocks/SM.
// ===========================================================================
#define R2 2
#define ROWS_PER_BLOCK_2 (R2 * 8)   // 16
#define TILES2 (OUTPUT_SIZE / ROWS_PER_BLOCK_2)   // 128
#define KQ (HIDDEN_SIZE / 4)        // 2048

__global__ __launch_bounds__(256, 4)
void rnn_h2o_kernel(const float* __restrict__ W2,     // [OUT, HIDDEN]
                    const float* __restrict__ bias1)  // [HIDDEN]
{
    __shared__ float4 s_in[BATCH][TK4];   // 16 KB (single buffer)

    const int tid  = threadIdx.x;
    const int lane = tid & 31;
    const int warp = tid >> 5;
    const int tile = blockIdx.x & (TILES2 - 1);
    const int q    = blockIdx.x >> 7;
    const int row0 = tile * ROWS_PER_BLOCK_2 + warp * R2;
    const int kbase = q * KQ;

    const int NCHUNK = KQ / TK;   // 4

    float acc[R2][BATCH];
    #pragma unroll
    for (int r = 0; r < R2; r++)
        #pragma unroll
        for (int b = 0; b < BATCH; b++)
            acc[r][b] = 0.0f;

    const float* W0 = W2 + (size_t)(row0 + 0) * HIDDEN_SIZE + kbase;
    const float* W1 = W2 + (size_t)(row0 + 1) * HIDDEN_SIZE + kbase;

    for (int c = 0; c < NCHUNK; ++c) {
        __syncthreads();        // previous chunk fully consumed
        // ---- stage: hidden = tanh(p1[0]+p1[1]+bias1), 4 float4/thread -----
        const int kf4 = (kbase + c * TK) >> 2;     // float4 index of chunk base
        #pragma unroll
        for (int t = 0; t < 4; ++t) {
            int f  = tid + t * 256;
            int b  = f >> 7;
            int k4 = f & (TK4 - 1);
            float4 p0 = __ldg((const float4*)&g_p1[0][b][0] + kf4 + k4);
            float4 p1 = __ldg((const float4*)&g_p1[1][b][0] + kf4 + k4);
            float4 bv = __ldg((const float4*)bias1 + kf4 + k4);
            float4 h;
            h.x = tanhf(p0.x + p1.x + bv.x);
            h.y = tanhf(p0.y + p1.y + bv.y);
            h.z = tanhf(p0.z + p1.z + bv.z);
            h.w = tanhf(p0.w + p1.w + bv.w);
            s_in[b][k4] = h;
        }
        __syncthreads();

        const float* Wc0 = W0 + (size_t)c * TK;
        const float* Wc1 = W1 + (size_t)c * TK;

        #pragma unroll
        for (int i = 0; i < TK4 / 32; ++i) {
            const int k4 = i * 32 + lane;
            float4 w0 = __ldcs((const float4*)Wc0 + k4);
            float4 w1 = __ldcs((const float4*)Wc1 + k4);

            #pragma unroll
            for (int b = 0; b < BATCH; b++) {
                float4 v = s_in[b][k4];
                acc[0][b] = fmaf(w0.x, v.x, acc[0][b]);
                acc[0][b] = fmaf(w0.y, v.y, acc[0][b]);
                acc[0][b] = fmaf(w0.z, v.z, acc[0][b]);
                acc[0][b] = fmaf(w0.w, v.w, acc[0][b]);
                acc[1][b] = fmaf(w1.x, v.x, acc[1][b]);
                acc[1][b] = fmaf(w1.y, v.y, acc[1][b]);
                acc[1][b] = fmaf(w1.z, v.z, acc[1][b]);
                acc[1][b] = fmaf(w1.w, v.w, acc[1][b]);
            }
        }
    }

    #pragma unroll
    for (int r = 0; r < R2; r++)
        #pragma unroll
        for (int b = 0; b < BATCH; b++)
            #pragma unroll
            for (int off = 16; off > 0; off >>= 1)
                acc[r][b] += __shfl_xor_sync(0xffffffffu, acc[r][b], off);

    #pragma unroll
    for (int r = 0; r < R2; r++) {
        const int row = row0 + r;
        #pragma unroll
        for (int b = 0; b < BATCH; b++)
            if (lane == b)
                g_p2[q][b][row] = acc[r][b];
    }
}

// ===========================================================================
// Kernel 3: out[b,o] = sum_4 p2[q][b,o] + bias2[o]   (float4)
// ===========================================================================
__global__ void rnn_reduce_kernel(const float* __restrict__ bias2,
                                  float* __restrict__ out)
{
    int idx = blockIdx.x * 256 + threadIdx.x;     // 4096 float4s
    int b  = idx >> 9;                             // / (OUT/4)
    int o4 = idx & (OUTPUT_SIZE / 4 - 1);
    float4 a = __ldg((const float4*)bias2 + o4);
    #pragma unroll
    for (int s = 0; s < 4; s++) {
        float4 p = ((const float4*)&g_p2[s][b][0])[o4];
        a.x += p.x; a.y += p.y; a.z += p.z; a.w += p.w;
    }
    ((float4*)out)[idx] = a;
}

// ---------------------------------------------------------------------------
// Inputs: x, initial_hidden, i2h_weight, i2h_bias, h2o_weight, h2o_bias
// ---------------------------------------------------------------------------
extern "C" void kernel_launch(void* const* d_in, const int* in_sizes, int n_in,
                              void* d_out, int out_size) {
    const float* x  = (const float*)d_in[0];
    const float* h0 = (const float*)d_in[1];
    const float* W1 = (const float*)d_in[2];
    const float* b1 = (const float*)d_in[3];
    const float* W2 = (const float*)d_in[4];
    const float* b2 = (const float*)d_in[5];
    float* out      = (float*)d_out;

    rnn_i2h_kernel<<<TILES1 * 2, 256>>>(x, h0, W1);
    rnn_h2o_kernel<<<TILES2 * 4, 256>>>(W2, b1);
    rnn_reduce_kernel<<<(BATCH * OUTPUT_SIZE / 4) / 256, 256>>>(b2, out);
}

// round 10
// speedup vs baseline: 1.4009x; 1.4009x over previous
#include <cuda_runtime.h>

#define BATCH 8
#define INPUT_SIZE 8192
#define HIDDEN_SIZE 8192
#define OUTPUT_SIZE 2048
#define KDIM 16384

// Intermediate hidden activations (8 x 8192 fp32 = 256 KB).
__device__ float g_hidden[BATCH * HIDDEN_SIZE];
// Partial sums for the K-split h2o GEMV: [split][batch][out]
__device__ float g_part[2][BATCH][OUTPUT_SIZE];

// ---------------------------------------------------------------------------
// cp.async helpers (16B variant)
// ---------------------------------------------------------------------------
__device__ __forceinline__ void cp_async16(void* smem_dst, const void* gmem_src) {
    unsigned s = (unsigned)__cvta_generic_to_shared(smem_dst);
    asm volatile("cp.async.cg.shared.global [%0], [%1], 16;\n" :: "r"(s), "l"(gmem_src));
}
__device__ __forceinline__ void cp_commit()  { asm volatile("cp.async.commit_group;\n"); }
__device__ __forceinline__ void cp_wait1()   { asm volatile("cp.async.wait_group 1;\n"); }
__device__ __forceinline__ void cp_wait0()   { asm volatile("cp.async.wait_group 0;\n"); }

#define TK  1024
#define TK4 (TK / 4)    // 256 float4 per batch per chunk

// ===========================================================================
// Kernel 1: hidden[b,h] = tanh( x[b,:]·W[h,0:8192] + h0[b,:]·W[h,8192:] + b1[h] )
// 256 threads (8 warps), 4 rows/warp -> 32 rows/block, grid = 256.
// cp.async double-buffered input staging, 16 chunks of 1024 (half the
// barrier events of the TK=512 version). Plain fmaf; regs at the 128 sweet
// spot (2 blocks/SM fills the register file).
// ===========================================================================
#define R1 4
#define ROWS_PER_BLOCK_1 (R1 * 8)   // 32

__global__ __launch_bounds__(256, 2)
void rnn_i2h_kernel(const float* __restrict__ x,
                    const float* __restrict__ h0,
                    const float* __restrict__ W,      // [HIDDEN_SIZE, KDIM]
                    const float* __restrict__ bias)
{
    __shared__ float4 s_in[2][BATCH][TK4];   // 2 x 32 KB

    const int tid  = threadIdx.x;
    const int lane = tid & 31;
    const int warp = tid >> 5;
    const int row0 = blockIdx.x * ROWS_PER_BLOCK_1 + warp * R1;

    const int NCHUNK = KDIM / TK;          // 16
    const int XCHUNK = INPUT_SIZE / TK;    // 8

    float acc[R1][BATCH];
    #pragma unroll
    for (int r = 0; r < R1; r++)
        #pragma unroll
        for (int b = 0; b < BATCH; b++)
            acc[r][b] = 0.0f;

    auto stage = [&](int c, int buf) {
        const float* src = (c < XCHUNK) ? (x + c * TK)
                                        : (h0 + (c - XCHUNK) * TK);
        #pragma unroll
        for (int t = 0; t < 8; ++t) {       // 2048 float4 / 256 threads
            int f  = tid + t * 256;
            int b  = f >> 8;                // / TK4 (=256)
            int k4 = f & (TK4 - 1);
            cp_async16(&s_in[buf][b][k4],
                       (const float4*)(src + (size_t)b * INPUT_SIZE) + k4);
        }
        cp_commit();
    };

    stage(0, 0);

    const float* Wr0 = W + (size_t)(row0 + 0) * KDIM;
    const float* Wr1 = W + (size_t)(row0 + 1) * KDIM;
    const float* Wr2 = W + (size_t)(row0 + 2) * KDIM;
    const float* Wr3 = W + (size_t)(row0 + 3) * KDIM;

    for (int c = 0; c < NCHUNK; ++c) {
        const int buf = c & 1;
        __syncthreads();                     // buffer (c+1)&1 is free now
        if (c + 1 < NCHUNK) { stage(c + 1, buf ^ 1); cp_wait1(); }
        else                { cp_wait0(); }
        __syncthreads();                     // chunk c visible to all warps

        const float* Wc0 = Wr0 + (size_t)c * TK;
        const float* Wc1 = Wr1 + (size_t)c * TK;
        const float* Wc2 = Wr2 + (size_t)c * TK;
        const float* Wc3 = Wr3 + (size_t)c * TK;

        #pragma unroll
        for (int i = 0; i < TK4 / 32; ++i) {          // 8 strips
            const int k4 = i * 32 + lane;
            float4 w0 = __ldcs((const float4*)Wc0 + k4);
            float4 w1 = __ldcs((const float4*)Wc1 + k4);
            float4 w2 = __ldcs((const float4*)Wc2 + k4);
            float4 w3 = __ldcs((const float4*)Wc3 + k4);

            #pragma unroll
            for (int b = 0; b < BATCH; b++) {
                float4 v = s_in[buf][b][k4];
                acc[0][b] = fmaf(w0.x, v.x, acc[0][b]);
                acc[0][b] = fmaf(w0.y, v.y, acc[0][b]);
                acc[0][b] = fmaf(w0.z, v.z, acc[0][b]);
                acc[0][b] = fmaf(w0.w, v.w, acc[0][b]);
                acc[1][b] = fmaf(w1.x, v.x, acc[1][b]);
                acc[1][b] = fmaf(w1.y, v.y, acc[1][b]);
                acc[1][b] = fmaf(w1.z, v.z, acc[1][b]);
                acc[1][b] = fmaf(w1.w, v.w, acc[1][b]);
                acc[2][b] = fmaf(w2.x, v.x, acc[2][b]);
                acc[2][b] = fmaf(w2.y, v.y, acc[2][b]);
                acc[2][b] = fmaf(w2.z, v.z, acc[2][b]);
                acc[2][b] = fmaf(w2.w, v.w, acc[2][b]);
                acc[3][b] = fmaf(w3.x, v.x, acc[3][b]);
                acc[3][b] = fmaf(w3.y, v.y, acc[3][b]);
                acc[3][b] = fmaf(w3.z, v.z, acc[3][b]);
                acc[3][b] = fmaf(w3.w, v.w, acc[3][b]);
            }
        }
    }

    // warp butterfly reduction
    #pragma unroll
    for (int r = 0; r < R1; r++)
        #pragma unroll
        for (int b = 0; b < BATCH; b++)
            #pragma unroll
            for (int off = 16; off > 0; off >>= 1)
                acc[r][b] += __shfl_xor_sync(0xffffffffu, acc[r][b], off);

    #pragma unroll
    for (int r = 0; r < R1; r++) {
        const int row = row0 + r;
        const float bv = __ldg(bias + row);
        #pragma unroll
        for (int b = 0; b < BATCH; b++)
            if (lane == b)
                g_hidden[b * HIDDEN_SIZE + row] = tanhf(acc[r][b] + bv);
    }
}

// ===========================================================================
// Kernel 2: K-split GEMV. part[s][b,o] = hidden[b, s*4096:(s+1)*4096]·W2[o,...]
// 256 threads, 2 rows/warp -> 16 rows/block, grid = 128 tiles x 2 splits.
// TK=1024: 4 chunks per half -> 8 syncs total.
// ===========================================================================
#define R2 2
#define ROWS_PER_BLOCK_2 (R2 * 8)   // 16
#define KSPLIT 2
#define KHALF (HIDDEN_SIZE / KSPLIT)   // 4096

__global__ __launch_bounds__(256, 2)
void rnn_h2o_kernel(const float* __restrict__ W2)   // [OUTPUT_SIZE, HIDDEN_SIZE]
{
    __shared__ float4 s_in[2][BATCH][TK4];   // 2 x 32 KB

    const int tid  = threadIdx.x;
    const int lane = tid & 31;
    const int warp = tid >> 5;
    const int tile = blockIdx.x & 127;          // 128 row tiles
    const int half = blockIdx.x >> 7;           // 0 or 1
    const int row0 = tile * ROWS_PER_BLOCK_2 + warp * R2;
    const int kbase = half * KHALF;

    const int NCHUNK = KHALF / TK;   // 4

    float acc[R2][BATCH];
    #pragma unroll
    for (int r = 0; r < R2; r++)
        #pragma unroll
        for (int b = 0; b < BATCH; b++)
            acc[r][b] = 0.0f;

    auto stage = [&](int c, int buf) {
        const float* src = g_hidden + kbase + c * TK;
        #pragma unroll
        for (int t = 0; t < 8; ++t) {
            int f  = tid + t * 256;
            int b  = f >> 8;
            int k4 = f & (TK4 - 1);
            cp_async16(&s_in[buf][b][k4],
                       (const float4*)(src + (size_t)b * HIDDEN_SIZE) + k4);
        }
        cp_commit();
    };

    stage(0, 0);

    const float* W0 = W2 + (size_t)(row0 + 0) * HIDDEN_SIZE + kbase;
    const float* W1 = W2 + (size_t)(row0 + 1) * HIDDEN_SIZE + kbase;

    for (int c = 0; c < NCHUNK; ++c) {
        const int buf = c & 1;
        __syncthreads();
        if (c + 1 < NCHUNK) { stage(c + 1, buf ^ 1); cp_wait1(); }
        else                { cp_wait0(); }
        __syncthreads();

        const float* Wc0 = W0 + (size_t)c * TK;
        const float* Wc1 = W1 + (size_t)c * TK;

        #pragma unroll
        for (int i = 0; i < TK4 / 32; ++i) {          // 8 strips
            const int k4 = i * 32 + lane;
            float4 w0 = __ldcs((const float4*)Wc0 + k4);
            float4 w1 = __ldcs((const float4*)Wc1 + k4);

            #pragma unroll
            for (int b = 0; b < BATCH; b++) {
                float4 v = s_in[buf][b][k4];
                acc[0][b] = fmaf(w0.x, v.x, acc[0][b]);
                acc[0][b] = fmaf(w0.y, v.y, acc[0][b]);
                acc[0][b] = fmaf(w0.z, v.z, acc[0][b]);
                acc[0][b] = fmaf(w0.w, v.w, acc[0][b]);
                acc[1][b] = fmaf(w1.x, v.x, acc[1][b]);
                acc[1][b] = fmaf(w1.y, v.y, acc[1][b]);
                acc[1][b] = fmaf(w1.z, v.z, acc[1][b]);
                acc[1][b] = fmaf(w1.w, v.w, acc[1][b]);
            }
        }
    }

    #pragma unroll
    for (int r = 0; r < R2; r++)
        #pragma unroll
        for (int b = 0; b < BATCH; b++)
            #pragma unroll
            for (int off = 16; off > 0; off >>= 1)
                acc[r][b] += __shfl_xor_sync(0xffffffffu, acc[r][b], off);

    #pragma unroll
    for (int r = 0; r < R2; r++) {
        const int row = row0 + r;
        #pragma unroll
        for (int b = 0; b < BATCH; b++)
            if (lane == b)
                g_part[half][b][row] = acc[r][b];
    }
}

// ===========================================================================
// Kernel 3: out[b,o] = part[0][b,o] + part[1][b,o] + bias2[o]
// ===========================================================================
__global__ void rnn_reduce_kernel(const float* __restrict__ bias2,
                                  float* __restrict__ out)
{
    int idx = blockIdx.x * blockDim.x + threadIdx.x;   // 16384 total
    int b = idx >> 11;               // / OUTPUT_SIZE
    int o = idx & (OUTPUT_SIZE - 1);
    out[idx] = g_part[0][b][o] + g_part[1][b][o] + __ldg(bias2 + o);
}

// ---------------------------------------------------------------------------
// Inputs: x, initial_hidden, i2h_weight, i2h_bias, h2o_weight, h2o_bias
// ---------------------------------------------------------------------------
extern "C" void kernel_launch(void* const* d_in, const int* in_sizes, int n_in,
                              void* d_out, int out_size) {
    const float* x    = (const float*)d_in[0];
    const float* h0   = (const float*)d_in[1];
    const float* W1   = (const float*)d_in[2];
    const float* b1   = (const float*)d_in[3];
    const float* W2   = (const float*)d_in[4];
    const float* b2   = (const float*)d_in[5];
    float* out        = (float*)d_out;

    rnn_i2h_kernel<<<HIDDEN_SIZE / ROWS_PER_BLOCK_1, 256>>>(x, h0, W1, b1);
    rnn_h2o_kernel<<<(OUTPUT_SIZE / ROWS_PER_BLOCK_2) * KSPLIT, 256>>>(W2);
    rnn_reduce_kernel<<<(BATCH * OUTPUT_SIZE) / 256, 256>>>(b2, out);
}